// round 17
// baseline (speedup 1.0000x reference)
#include <cuda_runtime.h>
#include <cuda_fp16.h>
#include <stdint.h>

#define SQ 2048
#define DH 64
#define NH_ 16
#define NB_ 4
#define KT 32
#define NTILES (SQ/KT)
#define OUT_ELEMS (NB_*NH_*SQ*DH)
#define RSTRIDE 144
#define QSCALE 0.18033688011112042f   // 0.125 * log2(e); exp(s) = exp2(S)

__device__ unsigned g_maskbits[(size_t)NB_ * SQ * (SQ / 32)];   // 2 MB
__device__ float    g_linv[(size_t)NB_ * NH_ * SQ];             // 512 KB
__device__ uint2    g_kh16[(size_t)NB_ * NH_ * SQ * DH / 4];    // 16 MB fp16 (K*QSCALE)
__device__ uint2    g_vh16[(size_t)NB_ * NH_ * SQ * DH / 4];    // 16 MB fp16 V

// pass0 smem: Q hi + K hi double buffer
#define P0_QH 0
#define P0_KH(bf) (18432 + (bf)*4608)
#define SMEM_0 27648
// pass1 smem: Q hi + K hi double + V hi double
#define SQH 0
#define SKH(bf) (18432 + (bf)*4608)
#define SVH(bf) (27648 + (bf)*4608)
#define SMEM_1 36864

// ---------------- PTX helpers ----------------
__device__ __forceinline__ void ldsm4(uint32_t* r, uint32_t a) {
    asm volatile("ldmatrix.sync.aligned.m8n8.x4.shared.b16 {%0,%1,%2,%3}, [%4];"
                 : "=r"(r[0]), "=r"(r[1]), "=r"(r[2]), "=r"(r[3]) : "r"(a));
}
__device__ __forceinline__ void ldsm4t(uint32_t* r, uint32_t a) {
    asm volatile("ldmatrix.sync.aligned.m8n8.x4.trans.shared.b16 {%0,%1,%2,%3}, [%4];"
                 : "=r"(r[0]), "=r"(r[1]), "=r"(r[2]), "=r"(r[3]) : "r"(a));
}
__device__ __forceinline__ void mma16816(float* c, const uint32_t* a, const uint32_t* b) {
    asm volatile("mma.sync.aligned.m16n8k16.row.col.f32.f16.f16.f32 "
                 "{%0,%1,%2,%3}, {%4,%5,%6,%7}, {%8,%9}, {%0,%1,%2,%3};"
                 : "+f"(c[0]), "+f"(c[1]), "+f"(c[2]), "+f"(c[3])
                 : "r"(a[0]), "r"(a[1]), "r"(a[2]), "r"(a[3]), "r"(b[0]), "r"(b[1]));
}
__device__ __forceinline__ float ex2(float x) {
    float y;
    asm("ex2.approx.ftz.f32 %0, %1;" : "=f"(y) : "f"(x));
    return y;
}
__device__ __forceinline__ uint32_t packh(float x, float y) {
    __half2 h = __halves2half2(__float2half_rn(x), __float2half_rn(y));
    return *reinterpret_cast<uint32_t*>(&h);
}
__device__ __forceinline__ void sts_f4h(char* sm, int off, int lin, float4 x) {
    uint32_t a = (uint32_t)(lin >> 4) * RSTRIDE + (uint32_t)(lin & 15) * 8;
    *reinterpret_cast<uint2*>(sm + off + a) = make_uint2(packh(x.x, x.y), packh(x.z, x.w));
}
__device__ __forceinline__ void cpasync16(uint32_t dst, const void* src) {
    asm volatile("cp.async.cg.shared.global [%0], [%1], 16;" :: "r"(dst), "l"(src) : "memory");
}
#define CP_COMMIT() asm volatile("cp.async.commit_group;" ::: "memory")
#define CP_WAIT0()  asm volatile("cp.async.wait_group 0;"  ::: "memory")

__device__ __forceinline__ unsigned long long pack_f2(float x, float y) {
    float2 f = make_float2(x, y);
    return *reinterpret_cast<unsigned long long*>(&f);
}

// ---------------- prep ----------------
__global__ void maskpack_kernel(const int* __restrict__ mask) {
    int gwarp = blockIdx.x * 8 + (threadIdx.x >> 5);
    int lane = threadIdx.x & 31;
    size_t base = (size_t)gwarp * 128;
    unsigned b0 = __ballot_sync(0xffffffffu, mask[base + lane] != 0);
    unsigned b1 = __ballot_sync(0xffffffffu, mask[base + 32 + lane] != 0);
    unsigned b2 = __ballot_sync(0xffffffffu, mask[base + 64 + lane] != 0);
    unsigned b3 = __ballot_sync(0xffffffffu, mask[base + 96 + lane] != 0);
    if (lane == 0)
        *reinterpret_cast<uint4*>(&g_maskbits[(size_t)gwarp * 4]) = make_uint4(b0, b1, b2, b3);
}

__global__ void prep_kv(const float* __restrict__ kg, const float* __restrict__ vg) {
    size_t i = (size_t)blockIdx.x * 256 + threadIdx.x;
    float4 kk = reinterpret_cast<const float4*>(kg)[i];
    float4 vv = reinterpret_cast<const float4*>(vg)[i];
    g_kh16[i] = make_uint2(packh(kk.x * QSCALE, kk.y * QSCALE),
                           packh(kk.z * QSCALE, kk.w * QSCALE));
    g_vh16[i] = make_uint2(packh(vv.x, vv.y), packh(vv.z, vv.w));
}

// ---------------- pass0: unchanged from R16 ----------------
__global__ __launch_bounds__(256, 4)
void sdpa_pass0(const float* __restrict__ qg)
{
    extern __shared__ char sm[];
    const uint32_t sb = (uint32_t)__cvta_generic_to_shared(sm);
    const int tid = threadIdx.x, warp = tid >> 5, lane = tid & 31;
    const int g = lane >> 2, t4 = lane & 3;
    const int qt = blockIdx.x, h = blockIdx.y, b = blockIdx.z;
    const int q0 = qt * 128;
    const size_t bh = (size_t)(b * NH_ + h);
    const float* qb = qg + (bh * SQ + (size_t)q0) * DH;
    const char* kh16 = reinterpret_cast<const char*>(g_kh16) + bh * SQ * 128;
    const int r0 = warp * 16 + g, r1 = r0 + 8;
    const int krow = tid >> 3, kchk = tid & 7;

#pragma unroll
    for (int i = 0; i < 8; i++) {
        int lin = i * 256 + tid;
        sts_f4h(sm, P0_QH, lin, reinterpret_cast<const float4*>(qb)[lin]);
    }
    cpasync16(sb + P0_KH(0) + (uint32_t)krow * RSTRIDE + kchk * 16,
              kh16 + (size_t)krow * 128 + kchk * 16);
    CP_COMMIT();

    float lsum0 = 0.0f, lsum1 = 0.0f;
    const uint32_t qHaddr = sb + P0_QH + (uint32_t)(warp * 16 + (lane & 15)) * RSTRIDE
                          + (uint32_t)(lane >> 4) * 16;
    const uint32_t kfoff = (uint32_t)(lane & 7) * RSTRIDE + (uint32_t)(lane >> 3) * 16;
    const unsigned* mw0 = &g_maskbits[((size_t)b * SQ + q0 + r0) * (SQ / 32)];
    const unsigned* mw1 = &g_maskbits[((size_t)b * SQ + q0 + r1) * (SQ / 32)];

    unsigned w0 = mw0[0], w1 = mw1[0];
    for (int t = 0; t < NTILES; t++) {
        const int cur = t & 1;
        unsigned w0c = w0, w1c = w1;
        CP_WAIT0();
        __syncthreads();
        if (t + 1 < NTILES) {
            cpasync16(sb + P0_KH(cur ^ 1) + (uint32_t)krow * RSTRIDE + kchk * 16,
                      kh16 + ((size_t)(t + 1) * KT + krow) * 128 + kchk * 16);
            CP_COMMIT();
            w0 = mw0[t + 1]; w1 = mw1[t + 1];
        }

        float S[4][4];
#pragma unroll
        for (int ng = 0; ng < 4; ng++)
#pragma unroll
            for (int j = 0; j < 4; j++) S[ng][j] = 0.0f;

#pragma unroll
        for (int kp = 0; kp < 2; kp++) {
            uint32_t qh0[4], qh1[4];
            ldsm4(qh0, qHaddr + kp * 64);
            ldsm4(qh1, qHaddr + kp * 64 + 32);
#pragma unroll
            for (int ng = 0; ng < 4; ng++) {
                uint32_t kh[4];
                ldsm4(kh, sb + P0_KH(cur) + (uint32_t)(ng * 8) * RSTRIDE + kp * 64 + kfoff);
                mma16816(S[ng], qh0, kh + 0);
                mma16816(S[ng], qh1, kh + 2);
            }
        }

#pragma unroll
        for (int ng = 0; ng < 4; ng++) {
            int j = 8 * ng + 2 * t4;
            lsum0 += (((w0c >> j) & 1u)       ? ex2(S[ng][0]) : 0.0f)
                   + (((w0c >> (j + 1)) & 1u) ? ex2(S[ng][1]) : 0.0f);
            lsum1 += (((w1c >> j) & 1u)       ? ex2(S[ng][2]) : 0.0f)
                   + (((w1c >> (j + 1)) & 1u) ? ex2(S[ng][3]) : 0.0f);
        }
    }

    lsum0 += __shfl_xor_sync(0xffffffffu, lsum0, 1);
    lsum0 += __shfl_xor_sync(0xffffffffu, lsum0, 2);
    lsum1 += __shfl_xor_sync(0xffffffffu, lsum1, 1);
    lsum1 += __shfl_xor_sync(0xffffffffu, lsum1, 2);
    if (t4 == 0) {
        g_linv[bh * SQ + q0 + r0] = 1.0f / lsum0;
        g_linv[bh * SQ + q0 + r1] = 1.0f / lsum1;
    }
}

// ---------------- pass1: + register-transposed coalesced attn stores ----------------
__global__ __launch_bounds__(256, 2)
void sdpa_pass1(const float* __restrict__ qg, float* __restrict__ outg)
{
    extern __shared__ char sm[];
    const uint32_t sb = (uint32_t)__cvta_generic_to_shared(sm);
    const int tid = threadIdx.x, warp = tid >> 5, lane = tid & 31;
    const int g = lane >> 2, t4 = lane & 3;
    const int qt = blockIdx.x, h = blockIdx.y, b = blockIdx.z;
    const int q0 = qt * 128;
    const size_t bh = (size_t)(b * NH_ + h);
    const float* qb = qg + (bh * SQ + (size_t)q0) * DH;
    const char* kh16 = reinterpret_cast<const char*>(g_kh16) + bh * SQ * 128;
    const char* vh16 = reinterpret_cast<const char*>(g_vh16) + bh * SQ * 128;
    const int r0 = warp * 16 + g, r1 = r0 + 8;
    const int krow = tid >> 3, kchk = tid & 7;

    const float invl0 = g_linv[bh * SQ + q0 + r0];
    const float invl1 = g_linv[bh * SQ + q0 + r1];

#pragma unroll
    for (int i = 0; i < 8; i++) {
        int lin = i * 256 + tid;
        sts_f4h(sm, SQH, lin, reinterpret_cast<const float4*>(qb)[lin]);
    }
    cpasync16(sb + SKH(0) + (uint32_t)krow * RSTRIDE + kchk * 16,
              kh16 + (size_t)krow * 128 + kchk * 16);
    cpasync16(sb + SVH(0) + (uint32_t)krow * RSTRIDE + kchk * 16,
              vh16 + (size_t)krow * 128 + kchk * 16);
    CP_COMMIT();

    float O[8][4];
#pragma unroll
    for (int n = 0; n < 8; n++)
#pragma unroll
        for (int j = 0; j < 4; j++) O[n][j] = 0.0f;

    const uint32_t qHaddr = sb + SQH + (uint32_t)(warp * 16 + (lane & 15)) * RSTRIDE
                          + (uint32_t)(lane >> 4) * 16;
    const uint32_t kfoff = (uint32_t)(lane & 7) * RSTRIDE + (uint32_t)(lane >> 3) * 16;
    const uint32_t vfoff = (uint32_t)(8 * (lane >> 3) + (lane & 7)) * RSTRIDE;
    const unsigned* mw0 = &g_maskbits[((size_t)b * SQ + q0 + r0) * (SQ / 32)];
    const unsigned* mw1 = &g_maskbits[((size_t)b * SQ + q0 + r1) * (SQ / 32)];
    float* attnw = outg + (size_t)OUT_ELEMS + (bh * SQ + (size_t)(q0 + warp * 16)) * SQ;
    float* at0 = attnw + (size_t)g * SQ;
    float* at1 = attnw + (size_t)(g + 8) * SQ;
    (void)at0; (void)at1;

    // transpose output addressing (lane-bit derived, loop-invariant)
    const int lb0 = lane & 1, lb1 = (lane >> 1) & 1, lb2 = (lane >> 2) & 1;
    const int lb3 = (lane >> 3) & 1, lb4 = (lane >> 4) & 1;
    const int colstart = 16 * lb4 + 8 * lb0 + 4 * lb1;
    const int rowlow = 2 * lb3 + lb2;

    unsigned w0 = mw0[0], w1 = mw1[0];
    for (int t = 0; t < NTILES; t++) {
        const int cur = t & 1;
        unsigned w0c = w0, w1c = w1;
        CP_WAIT0();
        __syncthreads();
        if (t + 1 < NTILES) {
            cpasync16(sb + SKH(cur ^ 1) + (uint32_t)krow * RSTRIDE + kchk * 16,
                      kh16 + ((size_t)(t + 1) * KT + krow) * 128 + kchk * 16);
            cpasync16(sb + SVH(cur ^ 1) + (uint32_t)krow * RSTRIDE + kchk * 16,
                      vh16 + ((size_t)(t + 1) * KT + krow) * 128 + kchk * 16);
            CP_COMMIT();
            w0 = mw0[t + 1]; w1 = mw1[t + 1];
        }

        // ---- S = Q_h K_h^T ----
        float S[4][4];
#pragma unroll
        for (int ng = 0; ng < 4; ng++)
#pragma unroll
            for (int j = 0; j < 4; j++) S[ng][j] = 0.0f;

#pragma unroll
        for (int kp = 0; kp < 2; kp++) {
            uint32_t qh0[4], qh1[4];
            ldsm4(qh0, qHaddr + kp * 64);
            ldsm4(qh1, qHaddr + kp * 64 + 32);
#pragma unroll
            for (int ng = 0; ng < 4; ng++) {
                uint32_t kh[4];
                ldsm4(kh, sb + SKH(cur) + (uint32_t)(ng * 8) * RSTRIDE + kp * 64 + kfoff);
                mma16816(S[ng], qh0, kh + 0);
                mma16816(S[ng], qh1, kh + 2);
            }
        }

        // ---- p = mask*exp2(S)*invl ----
#pragma unroll
        for (int ng = 0; ng < 4; ng++) {
            int j = 8 * ng + 2 * t4;
            S[ng][0] = ((w0c >> j) & 1u)       ? ex2(S[ng][0]) * invl0 : 0.0f;
            S[ng][1] = ((w0c >> (j + 1)) & 1u) ? ex2(S[ng][1]) * invl0 : 0.0f;
            S[ng][2] = ((w1c >> j) & 1u)       ? ex2(S[ng][2]) * invl1 : 0.0f;
            S[ng][3] = ((w1c >> (j + 1)) & 1u) ? ex2(S[ng][3]) * invl1 : 0.0f;
        }

        // ---- pack + PV MMA ----
        uint32_t ahi[2][4];
#pragma unroll
        for (int f = 0; f < 2; f++) {
            ahi[f][0] = packh(S[2*f][0],   S[2*f][1]);
            ahi[f][1] = packh(S[2*f][2],   S[2*f][3]);
            ahi[f][2] = packh(S[2*f+1][0], S[2*f+1][1]);
            ahi[f][3] = packh(S[2*f+1][2], S[2*f+1][3]);
        }
#pragma unroll
        for (int n = 0; n < 8; n++) {
            uint32_t bh4[4];
            ldsm4t(bh4, sb + SVH(cur) + vfoff + 16 * n);
            mma16816(O[n], ahi[0], bh4 + 0);
            mma16816(O[n], ahi[1], bh4 + 2);
        }

        // ---- register transpose: E[p][n1][n0] -> E[r3][r2][c0] ----
        unsigned long long E[2][2][2];
#pragma unroll
        for (int p = 0; p < 2; p++)
#pragma unroll
            for (int n1 = 0; n1 < 2; n1++)
#pragma unroll
                for (int n0 = 0; n0 < 2; n0++)
                    E[p][n1][n0] = pack_f2(S[2*n1+n0][2*p], S[2*n1+n0][2*p+1]);

        // Swap A: lane bit0 <-> item n0
#pragma unroll
        for (int p = 0; p < 2; p++)
#pragma unroll
            for (int n1 = 0; n1 < 2; n1++) {
                unsigned long long snd = E[p][n1][lb0 ^ 1];
                E[p][n1][lb0 ^ 1] = __shfl_xor_sync(0xffffffffu, snd, 1);
            }
        // Swap B: lane bit4 <-> item n1
#pragma unroll
        for (int p = 0; p < 2; p++)
#pragma unroll
            for (int k = 0; k < 2; k++) {
                unsigned long long snd = E[p][lb4 ^ 1][k];
                E[p][lb4 ^ 1][k] = __shfl_xor_sync(0xffffffffu, snd, 16);
            }

        // ---- coalesced attn stores: 4x STG.128, 4 full rows each ----
#pragma unroll
        for (int u1 = 0; u1 < 2; u1++)
#pragma unroll
            for (int u0 = 0; u0 < 2; u0++) {
                int row = 8 * u1 + 4 * u0 + rowlow;   // warp-local row 0..15
                float2 lo = *reinterpret_cast<float2*>(&E[u1][u0][0]);
                float2 hi = *reinterpret_cast<float2*>(&E[u1][u0][1]);
                float4 v4 = make_float4(lo.x, lo.y, hi.x, hi.y);
                __stcs(reinterpret_cast<float4*>(&attnw[(size_t)row * SQ + t * KT + colstart]), v4);
            }
    }

    float* outb = outg + (bh * SQ + (size_t)q0) * DH;
#pragma unroll
    for (int n = 0; n < 8; n++) {
        int col = 8 * n + 2 * t4;
        *reinterpret_cast<float2*>(&outb[(size_t)r0 * DH + col]) = make_float2(O[n][0], O[n][1]);
        *reinterpret_cast<float2*>(&outb[(size_t)r1 * DH + col]) = make_float2(O[n][2], O[n][3]);
    }
}

extern "C" void kernel_launch(void* const* d_in, const int* in_sizes, int n_in,
                              void* d_out, int out_size) {
    const float* q   = (const float*)d_in[0];
    const float* k   = (const float*)d_in[1];
    const float* v   = (const float*)d_in[2];
    const int*   msk = (const int*)d_in[3];
    float* out = (float*)d_out;

    cudaFuncSetAttribute(sdpa_pass0, cudaFuncAttributeMaxDynamicSharedMemorySize, SMEM_0);
    cudaFuncSetAttribute(sdpa_pass1, cudaFuncAttributeMaxDynamicSharedMemorySize, SMEM_1);

    maskpack_kernel<<<(NB_ * SQ * SQ) / (128 * 8), 256>>>(msk);
    prep_kv<<<(NB_ * NH_ * SQ * DH / 4) / 256, 256>>>(k, v);
    dim3 grid(SQ / 128, NH_, NB_);
    sdpa_pass0<<<grid, 256, SMEM_0>>>(q);
    sdpa_pass1<<<grid, 256, SMEM_1>>>(q, out);
}